// round 13
// baseline (speedup 1.0000x reference)
#include <cuda_runtime.h>

// AtteMatchLay: multi-perspective cosine matching. N=8192 rows, D=768, P=20.
// out[n,p] = dot/(max(sqrt(n1),eps)*max(sqrt(n2),eps)), sums over d weighted by w[p,d]^2.
//
// Round-13: D-PAIR f32x2 packing (acc = (even-d, odd-d) partial sums per row).
// Every operand is now a NATURAL 8-byte load: w[p,d0:d1] -> ull, r/m float2 -> ull.
// Zero pack/packab MOVs (was 14/iter). Epilogue folds x+y per accumulator.
// 2 rows x 5 persp per warp, 4 P-groups; 2-stage data + 2-buf w prefetch.

#define PDIM  20
#define DDIM  768
#define PP    5             // perspectives per warp (P-group size)
#define NPG   4             // number of P-groups
#define NITER (DDIM / 64)   // 12
#define EPS   1e-8f

typedef unsigned long long ull;

// ---- packed f32x2 helpers (only reachable via PTX) ----
__device__ __forceinline__ float2 u2f(ull v) {
    float2 f; asm("mov.b64 {%0, %1}, %2;" : "=f"(f.x), "=f"(f.y) : "l"(v)); return f;
}
__device__ __forceinline__ ull mul2(ull a, ull b) {
    ull r; asm("mul.rn.f32x2 %0, %1, %2;" : "=l"(r) : "l"(a), "l"(b)); return r;
}
__device__ __forceinline__ void fma2(ull& acc, ull a, ull b) {
    asm("fma.rn.f32x2 %0, %1, %2, %0;" : "+l"(acc) : "l"(a), "l"(b));
}
__device__ __forceinline__ ull add2(ull a, ull b) {
    ull r; asm("add.rn.f32x2 %0, %1, %2;" : "=l"(r) : "l"(a), "l"(b)); return r;
}

// Squared weights, [P][D] float layout (61.5 KB, L1/L2-resident).
__device__ float g_w2[PDIM * DDIM];

__global__ void prep_w2_kernel(const float* __restrict__ weight) {
    int t = blockIdx.x * blockDim.x + threadIdx.x;
    if (t < PDIM * DDIM) {
        float w = weight[t];
        g_w2[t] = w * w;
    }
}

__global__ void __launch_bounds__(128, 4)
cosmatch_kernel(const float* __restrict__ repres,
                const float* __restrict__ max_att,
                float* __restrict__ out,
                int N) {
    const int tid  = threadIdx.x;
    const int warp = tid >> 5;
    const int lane = tid & 31;
    const int pg   = blockIdx.y;              // perspective group (0..3)
    const int rowbase = blockIdx.x * 8 + warp * 2;

    const float* rp = repres  + (size_t)rowbase * DDIM + lane * 2;
    const float* mp = max_att + (size_t)rowbase * DDIM + lane * 2;
    const float* wg = g_w2 + pg * PP * DDIM + lane * 2;

    // Accumulators: [row][p], each packs (even-d, odd-d) partial sums
    ull ad0[PP], ar0[PP], am0[PP];
    ull ad1[PP], ar1[PP], am1[PP];
#pragma unroll
    for (int p = 0; p < PP; p++) {
        ad0[p] = 0ull; ar0[p] = 0ull; am0[p] = 0ull;
        ad1[p] = 0ull; ar1[p] = 0ull; am1[p] = 0ull;
    }

    // 2-stage data prefetch (natural ull loads of (d0,d1) float pairs)
    ull PR0[2], PR1[2], PM0[2], PM1[2];
#pragma unroll
    for (int s = 0; s < 2; s++) {
        PR0[s] = *(const ull*)(rp + s * 64);
        PR1[s] = *(const ull*)(rp + DDIM + s * 64);
        PM0[s] = *(const ull*)(mp + s * 64);
        PM1[s] = *(const ull*)(mp + DDIM + s * 64);
    }

    // Double-buffered w2 prefetch (natural ull loads)
    ull WB[2][PP];
#pragma unroll
    for (int p = 0; p < PP; p++)
        WB[0][p] = *(const ull*)(wg + p * DDIM);

#pragma unroll 2
    for (int k = 0; k < NITER; k++) {
        const int buf = k & 1;

        // Consume current stages (resident registers, zero repack work)
        const ull ra0 = PR0[buf], ra1 = PR1[buf];
        const ull ma0 = PM0[buf], ma1 = PM1[buf];
        ull Wc[PP];
#pragma unroll
        for (int p = 0; p < PP; p++) Wc[p] = WB[buf][p];

        // Prefetch data for iteration k+2 (clamped; tail re-reads harmless)
        {
            int kp = k + 2; if (kp > NITER - 1) kp = NITER - 1;
            const int d = kp * 64;
            PR0[buf] = *(const ull*)(rp + d);
            PR1[buf] = *(const ull*)(rp + DDIM + d);
            PM0[buf] = *(const ull*)(mp + d);
            PM1[buf] = *(const ull*)(mp + DDIM + d);
        }
        // Prefetch w2 for iteration k+1 into the other buffer
        {
            int kp = k + 1; if (kp > NITER - 1) kp = NITER - 1;
            const float* wk = wg + kp * 64;
#pragma unroll
            for (int p = 0; p < PP; p++)
                WB[buf ^ 1][p] = *(const ull*)(wk + p * DDIM);
        }

        const ull rm0 = mul2(ra0, ma0), rr0 = mul2(ra0, ra0), mm0 = mul2(ma0, ma0);
        const ull rm1 = mul2(ra1, ma1), rr1 = mul2(ra1, ra1), mm1 = mul2(ma1, ma1);

#pragma unroll
        for (int p = 0; p < PP; p++) {
            const ull w = Wc[p];
            fma2(ad0[p], rm0, w);
            fma2(ad1[p], rm1, w);
            fma2(ar0[p], rr0, w);
            fma2(ar1[p], rr1, w);
            fma2(am0[p], mm0, w);
            fma2(am1[p], mm1, w);
        }
    }

    // Butterfly reduction across lanes
#pragma unroll
    for (int mask = 16; mask > 0; mask >>= 1) {
#pragma unroll
        for (int p = 0; p < PP; p++) {
            ad0[p] = add2(ad0[p], (ull)__shfl_xor_sync(0xFFFFFFFFu, ad0[p], mask));
            ar0[p] = add2(ar0[p], (ull)__shfl_xor_sync(0xFFFFFFFFu, ar0[p], mask));
            am0[p] = add2(am0[p], (ull)__shfl_xor_sync(0xFFFFFFFFu, am0[p], mask));
            ad1[p] = add2(ad1[p], (ull)__shfl_xor_sync(0xFFFFFFFFu, ad1[p], mask));
            ar1[p] = add2(ar1[p], (ull)__shfl_xor_sync(0xFFFFFFFFu, ar1[p], mask));
            am1[p] = add2(am1[p], (ull)__shfl_xor_sync(0xFFFFFFFFu, am1[p], mask));
        }
    }

    // Epilogue: lane 0 folds (even,odd) halves and writes 2 rows x 5 perspectives
    if (lane == 0 && rowbase < N) {
        float* o0 = out + (size_t)(rowbase + 0) * PDIM + pg * PP;
        float* o1 = out + (size_t)(rowbase + 1) * PDIM + pg * PP;
#pragma unroll
        for (int p = 0; p < PP; p++) {
            const float2 d0 = u2f(ad0[p]), r0 = u2f(ar0[p]), m0 = u2f(am0[p]);
            const float2 d1 = u2f(ad1[p]), r1 = u2f(ar1[p]), m1 = u2f(am1[p]);
            const float dot0 = d0.x + d0.y, n10 = r0.x + r0.y, n20 = m0.x + m0.y;
            const float dot1 = d1.x + d1.y, n11 = r1.x + r1.y, n21 = m1.x + m1.y;
            o0[p] = dot0 / (fmaxf(sqrtf(n10), EPS) * fmaxf(sqrtf(n20), EPS));
            o1[p] = dot1 / (fmaxf(sqrtf(n11), EPS) * fmaxf(sqrtf(n21), EPS));
        }
    }
}

extern "C" void kernel_launch(void* const* d_in, const int* in_sizes, int n_in,
                              void* d_out, int out_size) {
    const float* repres  = (const float*)d_in[0];
    const float* max_att = (const float*)d_in[1];
    const float* weight  = (const float*)d_in[2];
    float* out = (float*)d_out;

    const int N = in_sizes[0] / DDIM;   // 8192 rows for the given shapes

    {
        const int total = PDIM * DDIM;
        prep_w2_kernel<<<(total + 255) / 256, 256>>>(weight);
    }
    {
        // 8 rows per block (4 warps x 2 rows), 4 P-group blocks cover P=20
        dim3 grid((N + 7) / 8, NPG);
        cosmatch_kernel<<<grid, 128>>>(repres, max_att, out, N);
    }
}

// round 14
// speedup vs baseline: 1.0126x; 1.0126x over previous
#include <cuda_runtime.h>

// AtteMatchLay: multi-perspective cosine matching. N=8192 rows, D=768, P=20.
// out[n,p] = dot/(max(sqrt(n1),eps)*max(sqrt(n2),eps)), sums over d weighted by w[p,d]^2.
//
// Round-14: R11 row-packed scheme, warp-tile widened to 4 ROWS x 5 persp.
// w2 amortized over 4 rows -> total L1 bytes drop 28% (453->327 MB); fma becomes
// the sole binding pipe. Accumulators: 5p x 2 row-packs x 3 sums = 30 ull = 60 regs.
// 2-stage data prefetch + double-buffered w2 prefetch; launch_bounds(128,4).

#define PDIM  20
#define DDIM  768
#define PP    5             // perspectives per warp (P-group size)
#define NPG   4             // number of P-groups
#define RROWS 4             // rows per warp
#define NPK   2             // row-packs (RROWS/2)
#define NITER (DDIM / 64)   // 12
#define EPS   1e-8f

typedef unsigned long long ull;

// ---- packed f32x2 helpers (only reachable via PTX) ----
__device__ __forceinline__ ull pack2(float x) {
    ull r; asm("mov.b64 %0, {%1, %1};" : "=l"(r) : "f"(x)); return r;
}
__device__ __forceinline__ ull packab(float a, float b) {
    ull r; asm("mov.b64 %0, {%1, %2};" : "=l"(r) : "f"(a), "f"(b)); return r;
}
__device__ __forceinline__ float2 u2f(ull v) {
    float2 f; asm("mov.b64 {%0, %1}, %2;" : "=f"(f.x), "=f"(f.y) : "l"(v)); return f;
}
__device__ __forceinline__ ull mul2(ull a, ull b) {
    ull r; asm("mul.rn.f32x2 %0, %1, %2;" : "=l"(r) : "l"(a), "l"(b)); return r;
}
__device__ __forceinline__ void fma2(ull& acc, ull a, ull b) {
    asm("fma.rn.f32x2 %0, %1, %2, %0;" : "+l"(acc) : "l"(a), "l"(b));
}
__device__ __forceinline__ ull add2(ull a, ull b) {
    ull r; asm("add.rn.f32x2 %0, %1, %2;" : "=l"(r) : "l"(a), "l"(b)); return r;
}

// Squared weights, [P][D] float layout (61.5 KB, L1/L2-resident).
__device__ float g_w2[PDIM * DDIM];

__global__ void prep_w2_kernel(const float* __restrict__ weight) {
    int t = blockIdx.x * blockDim.x + threadIdx.x;
    if (t < PDIM * DDIM) {
        float w = weight[t];
        g_w2[t] = w * w;
    }
}

__global__ void __launch_bounds__(128, 4)
cosmatch_kernel(const float* __restrict__ repres,
                const float* __restrict__ max_att,
                float* __restrict__ out,
                int N) {
    const int tid  = threadIdx.x;
    const int warp = tid >> 5;
    const int lane = tid & 31;
    const int pg   = blockIdx.y;                    // perspective group (0..3)
    const int rowbase = blockIdx.x * (4 * RROWS) + warp * RROWS;

    const float* rp = repres  + (size_t)rowbase * DDIM + lane * 2;
    const float* mp = max_att + (size_t)rowbase * DDIM + lane * 2;
    const float* wg = g_w2 + pg * PP * DDIM + lane * 2;

    // Accumulators: [p][row-pack], each f32x2 packs rows (2k, 2k+1)
    ull accd[PP][NPK], accr[PP][NPK], accm[PP][NPK];
#pragma unroll
    for (int p = 0; p < PP; p++)
#pragma unroll
        for (int k = 0; k < NPK; k++) {
            accd[p][k] = 0ull; accr[p][k] = 0ull; accm[p][k] = 0ull;
        }

    // 2-stage data prefetch: 4 rows of r and m per stage
    float2 PR[2][RROWS], PM[2][RROWS];
#pragma unroll
    for (int s = 0; s < 2; s++)
#pragma unroll
        for (int rr = 0; rr < RROWS; rr++) {
            PR[s][rr] = *(const float2*)(rp + rr * DDIM + s * 64);
            PM[s][rr] = *(const float2*)(mp + rr * DDIM + s * 64);
        }

    // Double-buffered w2 prefetch
    float2 WB[2][PP];
#pragma unroll
    for (int p = 0; p < PP; p++)
        WB[0][p] = *(const float2*)(wg + p * DDIM);

#pragma unroll 2
    for (int it = 0; it < NITER; it++) {
        const int buf = it & 1;

        // Consume current stages
        float2 R[RROWS], M[RROWS], Wc[PP];
#pragma unroll
        for (int rr = 0; rr < RROWS; rr++) { R[rr] = PR[buf][rr]; M[rr] = PM[buf][rr]; }
#pragma unroll
        for (int p = 0; p < PP; p++) Wc[p] = WB[buf][p];

        // Prefetch data for iteration it+2 (clamped; tail re-reads harmless)
        {
            int kp = it + 2; if (kp > NITER - 1) kp = NITER - 1;
            const int d = kp * 64;
#pragma unroll
            for (int rr = 0; rr < RROWS; rr++) {
                PR[buf][rr] = *(const float2*)(rp + rr * DDIM + d);
                PM[buf][rr] = *(const float2*)(mp + rr * DDIM + d);
            }
        }
        // Prefetch w2 for iteration it+1 into the other buffer
        {
            int kp = it + 1; if (kp > NITER - 1) kp = NITER - 1;
            const float* wk = wg + kp * 64;
#pragma unroll
            for (int p = 0; p < PP; p++)
                WB[buf ^ 1][p] = *(const float2*)(wk + p * DDIM);
        }

        // Row-packed operands per pack k: rows (2k, 2k+1), 2 d-values each
        ull rm[NPK][2], rr2[NPK][2], mm[NPK][2];
#pragma unroll
        for (int k = 0; k < NPK; k++) {
            const ull ra0 = packab(R[2*k].x, R[2*k+1].x), ra1 = packab(R[2*k].y, R[2*k+1].y);
            const ull ma0 = packab(M[2*k].x, M[2*k+1].x), ma1 = packab(M[2*k].y, M[2*k+1].y);
            rm[k][0]  = mul2(ra0, ma0);  rm[k][1]  = mul2(ra1, ma1);
            rr2[k][0] = mul2(ra0, ra0);  rr2[k][1] = mul2(ra1, ra1);
            mm[k][0]  = mul2(ma0, ma0);  mm[k][1]  = mul2(ma1, ma1);
        }

#pragma unroll
        for (int p = 0; p < PP; p++) {
            const ull wx = pack2(Wc[p].x);
            const ull wy = pack2(Wc[p].y);
#pragma unroll
            for (int k = 0; k < NPK; k++) {
                fma2(accd[p][k], rm[k][0],  wx);
                fma2(accd[p][k], rm[k][1],  wy);
                fma2(accr[p][k], rr2[k][0], wx);
                fma2(accr[p][k], rr2[k][1], wy);
                fma2(accm[p][k], mm[k][0],  wx);
                fma2(accm[p][k], mm[k][1],  wy);
            }
        }
    }

    // Butterfly reduction across lanes (accumulators stay row-packed)
#pragma unroll
    for (int mask = 16; mask > 0; mask >>= 1) {
#pragma unroll
        for (int p = 0; p < PP; p++)
#pragma unroll
            for (int k = 0; k < NPK; k++) {
                accd[p][k] = add2(accd[p][k], (ull)__shfl_xor_sync(0xFFFFFFFFu, accd[p][k], mask));
                accr[p][k] = add2(accr[p][k], (ull)__shfl_xor_sync(0xFFFFFFFFu, accr[p][k], mask));
                accm[p][k] = add2(accm[p][k], (ull)__shfl_xor_sync(0xFFFFFFFFu, accm[p][k], mask));
            }
    }

    // Epilogue: lane 0 writes 4 rows x 5 perspectives
    if (lane == 0 && rowbase < N) {
#pragma unroll
        for (int k = 0; k < NPK; k++) {
            float* o0 = out + (size_t)(rowbase + 2*k + 0) * PDIM + pg * PP;
            float* o1 = out + (size_t)(rowbase + 2*k + 1) * PDIM + pg * PP;
#pragma unroll
            for (int p = 0; p < PP; p++) {
                const float2 dd = u2f(accd[p][k]);
                const float2 n1 = u2f(accr[p][k]);
                const float2 n2 = u2f(accm[p][k]);
                o0[p] = dd.x / (fmaxf(sqrtf(n1.x), EPS) * fmaxf(sqrtf(n2.x), EPS));
                o1[p] = dd.y / (fmaxf(sqrtf(n1.y), EPS) * fmaxf(sqrtf(n2.y), EPS));
            }
        }
    }
}

extern "C" void kernel_launch(void* const* d_in, const int* in_sizes, int n_in,
                              void* d_out, int out_size) {
    const float* repres  = (const float*)d_in[0];
    const float* max_att = (const float*)d_in[1];
    const float* weight  = (const float*)d_in[2];
    float* out = (float*)d_out;

    const int N = in_sizes[0] / DDIM;   // 8192 rows for the given shapes

    {
        const int total = PDIM * DDIM;
        prep_w2_kernel<<<(total + 255) / 256, 256>>>(weight);
    }
    {
        // 16 rows per block (4 warps x 4 rows), 4 P-group blocks cover P=20
        dim3 grid((N + 15) / 16, NPG);
        cosmatch_kernel<<<grid, 128>>>(repres, max_att, out, N);
    }
}

// round 16
// speedup vs baseline: 1.0556x; 1.0425x over previous
#include <cuda_runtime.h>

// AtteMatchLay: multi-perspective cosine matching. N=8192 rows, D=768, P=20.
// out[n,p] = dot/(max(sqrt(n1),eps)*max(sqrt(n2),eps)), sums over d weighted by w[p,d]^2.
//
// Round-16: R11 (best) + deeper latency cover:
//  - 4-stage register prefetch on r/m (was 2) -> covers ~2x more DRAM latency
//  - __ldcs (evict-first) on streaming r/m so w2 stays L1-resident
//  - double-buffered w2 prefetch kept; block=256, launch_bounds(256,2) (<=128 regs)
// Warp-tile = 2 rows (f32x2 row-packed) x 5 perspectives; 4 P-groups.

#define PDIM  20
#define DDIM  768
#define PP    5             // perspectives per warp (P-group size)
#define NPG   4             // number of P-groups
#define NITER (DDIM / 64)   // 12
#define PFD   4             // prefetch depth (iterations ahead = PFD-... buffers)
#define EPS   1e-8f

typedef unsigned long long ull;

// ---- packed f32x2 helpers (only reachable via PTX) ----
__device__ __forceinline__ ull pack2(float x) {
    ull r; asm("mov.b64 %0, {%1, %1};" : "=l"(r) : "f"(x)); return r;
}
__device__ __forceinline__ ull packab(float a, float b) {
    ull r; asm("mov.b64 %0, {%1, %2};" : "=l"(r) : "f"(a), "f"(b)); return r;
}
__device__ __forceinline__ float2 u2f(ull v) {
    float2 f; asm("mov.b64 {%0, %1}, %2;" : "=f"(f.x), "=f"(f.y) : "l"(v)); return f;
}
__device__ __forceinline__ ull mul2(ull a, ull b) {
    ull r; asm("mul.rn.f32x2 %0, %1, %2;" : "=l"(r) : "l"(a), "l"(b)); return r;
}
__device__ __forceinline__ void fma2(ull& acc, ull a, ull b) {
    asm("fma.rn.f32x2 %0, %1, %2, %0;" : "+l"(acc) : "l"(a), "l"(b));
}
__device__ __forceinline__ ull add2(ull a, ull b) {
    ull r; asm("add.rn.f32x2 %0, %1, %2;" : "=l"(r) : "l"(a), "l"(b)); return r;
}
// Streaming (evict-first) float2 load — keeps w2 resident in L1
__device__ __forceinline__ float2 ldcs2(const float* p) {
    float2 v;
    asm volatile("ld.global.cs.v2.f32 {%0, %1}, [%2];"
                 : "=f"(v.x), "=f"(v.y) : "l"(p));
    return v;
}

// Squared weights, [P][D] float layout (61.5 KB, L1/L2-resident).
__device__ float g_w2[PDIM * DDIM];

__global__ void prep_w2_kernel(const float* __restrict__ weight) {
    int t = blockIdx.x * blockDim.x + threadIdx.x;
    if (t < PDIM * DDIM) {
        float w = weight[t];
        g_w2[t] = w * w;
    }
}

__global__ void __launch_bounds__(256, 2)
cosmatch_kernel(const float* __restrict__ repres,
                const float* __restrict__ max_att,
                float* __restrict__ out,
                int N) {
    const int tid  = threadIdx.x;
    const int warp = tid >> 5;
    const int lane = tid & 31;
    const int pg   = blockIdx.y;              // perspective group (0..3)
    const int rowbase = blockIdx.x * 16 + warp * 2;

    const float* rp = repres  + (size_t)rowbase * DDIM + lane * 2;
    const float* mp = max_att + (size_t)rowbase * DDIM + lane * 2;
    const float* wg = g_w2 + pg * PP * DDIM + lane * 2;

    ull accd[PP], accr[PP], accm[PP];
#pragma unroll
    for (int p = 0; p < PP; p++) { accd[p] = 0ull; accr[p] = 0ull; accm[p] = 0ull; }

    // 4-stage data prefetch buffers (row0/row1 of r and m), streaming loads
    float2 PR0[PFD], PR1[PFD], PM0[PFD], PM1[PFD];
#pragma unroll
    for (int s = 0; s < PFD; s++) {
        PR0[s] = ldcs2(rp + s * 64);
        PR1[s] = ldcs2(rp + DDIM + s * 64);
        PM0[s] = ldcs2(mp + s * 64);
        PM1[s] = ldcs2(mp + DDIM + s * 64);
    }

    // Double-buffered w2 prefetch (default caching -> L1-resident)
    float2 WB[2][PP];
#pragma unroll
    for (int p = 0; p < PP; p++)
        WB[0][p] = *(const float2*)(wg + p * DDIM);

#pragma unroll 4
    for (int k = 0; k < NITER; k++) {
        const int buf  = k & (PFD - 1);
        const int wbuf = k & 1;

        // Consume current stages (all resident in registers)
        const float2 R0 = PR0[buf], R1 = PR1[buf];
        const float2 M0 = PM0[buf], M1 = PM1[buf];
        float2 Wc[PP];
#pragma unroll
        for (int p = 0; p < PP; p++) Wc[p] = WB[wbuf][p];

        // Prefetch data for iteration k+PFD (clamped; tail re-reads harmless)
        {
            int kp = k + PFD; if (kp > NITER - 1) kp = NITER - 1;
            const int d = kp * 64;
            PR0[buf] = ldcs2(rp + d);
            PR1[buf] = ldcs2(rp + DDIM + d);
            PM0[buf] = ldcs2(mp + d);
            PM1[buf] = ldcs2(mp + DDIM + d);
        }
        // Prefetch w2 for iteration k+1 into the other buffer
        {
            int kp = k + 1; if (kp > NITER - 1) kp = NITER - 1;
            const float* wk = wg + kp * 64;
#pragma unroll
            for (int p = 0; p < PP; p++)
                WB[wbuf ^ 1][p] = *(const float2*)(wk + p * DDIM);
        }

        const ull ra0 = packab(R0.x, R1.x), ra1 = packab(R0.y, R1.y);
        const ull ma0 = packab(M0.x, M1.x), ma1 = packab(M0.y, M1.y);
        const ull rm0 = mul2(ra0, ma0), rm1 = mul2(ra1, ma1);
        const ull rr0 = mul2(ra0, ra0), rr1 = mul2(ra1, ra1);
        const ull mm0 = mul2(ma0, ma0), mm1 = mul2(ma1, ma1);

#pragma unroll
        for (int p = 0; p < PP; p++) {
            const ull wx = pack2(Wc[p].x);
            const ull wy = pack2(Wc[p].y);
            fma2(accd[p], rm0, wx);
            fma2(accd[p], rm1, wy);
            fma2(accr[p], rr0, wx);
            fma2(accr[p], rr1, wy);
            fma2(accm[p], mm0, wx);
            fma2(accm[p], mm1, wy);
        }
    }

    // Butterfly reduction across lanes (accumulators stay row-packed)
#pragma unroll
    for (int mask = 16; mask > 0; mask >>= 1) {
#pragma unroll
        for (int p = 0; p < PP; p++) {
            accd[p] = add2(accd[p], (ull)__shfl_xor_sync(0xFFFFFFFFu, accd[p], mask));
            accr[p] = add2(accr[p], (ull)__shfl_xor_sync(0xFFFFFFFFu, accr[p], mask));
            accm[p] = add2(accm[p], (ull)__shfl_xor_sync(0xFFFFFFFFu, accm[p], mask));
        }
    }

    // Epilogue: lane 0 writes 2 rows x 5 perspectives
    if (lane == 0 && rowbase < N) {
        float* o0 = out + (size_t)(rowbase + 0) * PDIM + pg * PP;
        float* o1 = out + (size_t)(rowbase + 1) * PDIM + pg * PP;
#pragma unroll
        for (int p = 0; p < PP; p++) {
            const float2 dd = u2f(accd[p]);
            const float2 n1 = u2f(accr[p]);
            const float2 n2 = u2f(accm[p]);
            o0[p] = dd.x / (fmaxf(sqrtf(n1.x), EPS) * fmaxf(sqrtf(n2.x), EPS));
            o1[p] = dd.y / (fmaxf(sqrtf(n1.y), EPS) * fmaxf(sqrtf(n2.y), EPS));
        }
    }
}

extern "C" void kernel_launch(void* const* d_in, const int* in_sizes, int n_in,
                              void* d_out, int out_size) {
    const float* repres  = (const float*)d_in[0];
    const float* max_att = (const float*)d_in[1];
    const float* weight  = (const float*)d_in[2];
    float* out = (float*)d_out;

    const int N = in_sizes[0] / DDIM;   // 8192 rows for the given shapes

    {
        const int total = PDIM * DDIM;
        prep_w2_kernel<<<(total + 255) / 256, 256>>>(weight);
    }
    {
        // 16 rows per block (8 warps x 2 rows), 4 P-group blocks cover P=20
        dim3 grid((N + 15) / 16, NPG);
        cosmatch_kernel<<<grid, 256>>>(repres, max_att, out, N);
    }
}